// round 4
// baseline (speedup 1.0000x reference)
#include <cuda_runtime.h>
#include <math.h>

#define N_NODES 100000
#define N_EDGES 1600000
#define IN_DIM  512
#define HID     64
#define NL      3

#define SCAN_CHUNK 1024
#define NB_SCAN ((N_NODES + SCAN_CHUNK - 1) / SCAN_CHUNK)   // 98

// Scratch (device globals: allowed; cudaMalloc is not)
__device__ __align__(16) float g_h[N_NODES * HID];
__device__ __align__(16) float g_agg[N_NODES * HID];
__device__ float g_inv[N_NODES];
__device__ int   g_deg[N_NODES];
__device__ int   g_off[N_NODES];
__device__ int   g_cur[N_NODES];
__device__ int   g_csr[N_EDGES];
__device__ int   g_bsum[NB_SCAN];
__device__ int   g_bpre[NB_SCAN];

// ---------------------------------------------------------------------------
// Encoder: h = x @ W_enc + b_enc   ([100k,512] @ [512,64])
// One thread per node row, 64 fp32 accumulators, W chunk (128x64) in smem.
// ---------------------------------------------------------------------------
__global__ void __launch_bounds__(256) k_encoder(const float* __restrict__ x,
                                                 const float* __restrict__ W,
                                                 const float* __restrict__ b) {
    __shared__ float Ws[128 * HID];  // 32 KB chunk of W_enc
    const int tid = threadIdx.x;
    const int row = blockIdx.x * 256 + tid;
    const int r   = (row < N_NODES) ? row : (N_NODES - 1);

    float acc[HID];
#pragma unroll
    for (int j = 0; j < HID; j++) acc[j] = b[j];

    const float4* xr = (const float4*)(x + (size_t)r * IN_DIM);

    for (int kc = 0; kc < IN_DIM / 128; kc++) {
        __syncthreads();
        const float4* Wc = (const float4*)(W + (size_t)kc * 128 * HID);
#pragma unroll
        for (int i = tid; i < 128 * HID / 4; i += 256)
            ((float4*)Ws)[i] = Wc[i];
        __syncthreads();

#pragma unroll 1
        for (int k4 = 0; k4 < 32; k4++) {
            const float4 xv = xr[kc * 32 + k4];
            const float* w0 = Ws + (k4 * 4) * HID;
#pragma unroll
            for (int j = 0; j < HID; j++) {
                float a = acc[j];
                a = fmaf(xv.x, w0[j],           a);
                a = fmaf(xv.y, w0[HID + j],     a);
                a = fmaf(xv.z, w0[2 * HID + j], a);
                a = fmaf(xv.w, w0[3 * HID + j], a);
                acc[j] = a;
            }
        }
    }

    if (row < N_NODES) {
        float4* hr = (float4*)(g_h + (size_t)row * HID);
#pragma unroll
        for (int j4 = 0; j4 < HID / 4; j4++)
            hr[j4] = make_float4(acc[4 * j4], acc[4 * j4 + 1],
                                 acc[4 * j4 + 2], acc[4 * j4 + 3]);
    }
}

// ---------------------------------------------------------------------------
// Degree + CSR construction  (edge_index is int32: [2, E] row-major)
// ---------------------------------------------------------------------------
__global__ void k_zero_deg() {
    int i = blockIdx.x * blockDim.x + threadIdx.x;
    if (i < N_NODES) { g_deg[i] = 0; g_cur[i] = 0; }
}

__global__ void k_count(const int* __restrict__ ei) {
    int e = blockIdx.x * blockDim.x + threadIdx.x;
    if (e < N_EDGES) atomicAdd(&g_deg[ei[N_EDGES + e]], 1);
}

__global__ void k_inv() {
    int i = blockIdx.x * blockDim.x + threadIdx.x;
    if (i < N_NODES) {
        int d = g_deg[i];
        g_inv[i] = (d > 0) ? (1.0f / (float)d) : 0.0f;
    }
}

// Scan pass 1: per-block exclusive scan of g_deg in 1024-element chunks.
__global__ void __launch_bounds__(256) k_scan1() {
    __shared__ int s_sum[256];
    const int b = blockIdx.x, t = threadIdx.x;
    const int base = b * SCAN_CHUNK + t * 4;
    int v[4], tot = 0;
#pragma unroll
    for (int j = 0; j < 4; j++) {
        int idx = base + j;
        v[j] = (idx < N_NODES) ? g_deg[idx] : 0;
        tot += v[j];
    }
    s_sum[t] = tot;
    __syncthreads();
    // Hillis-Steele inclusive scan over 256 thread totals
    for (int off = 1; off < 256; off <<= 1) {
        int x = (t >= off) ? s_sum[t - off] : 0;
        __syncthreads();
        s_sum[t] += x;
        __syncthreads();
    }
    int run = s_sum[t] - tot;  // exclusive prefix within block
#pragma unroll
    for (int j = 0; j < 4; j++) {
        int idx = base + j;
        if (idx < N_NODES) g_off[idx] = run;
        run += v[j];
    }
    if (t == 255) g_bsum[b] = s_sum[255];
}

// Scan pass 2: single block scans the 98 block sums (exclusive).
__global__ void __launch_bounds__(128) k_scan2() {
    __shared__ int s[128];
    const int t = threadIdx.x;
    int v = (t < NB_SCAN) ? g_bsum[t] : 0;
    s[t] = v;
    __syncthreads();
    for (int off = 1; off < 128; off <<= 1) {
        int x = (t >= off) ? s[t - off] : 0;
        __syncthreads();
        s[t] += x;
        __syncthreads();
    }
    if (t < NB_SCAN) g_bpre[t] = s[t] - v;
}

// Scan pass 3: add block prefixes.
__global__ void k_scan3() {
    int i = blockIdx.x * blockDim.x + threadIdx.x;
    if (i < N_NODES) g_off[i] += g_bpre[i / SCAN_CHUNK];
}

// Bin edges into CSR by destination.
__global__ void k_bin(const int* __restrict__ ei) {
    int e = blockIdx.x * blockDim.x + threadIdx.x;
    if (e < N_EDGES) {
        int s = ei[e];
        int d = ei[N_EDGES + e];
        int p = g_off[d] + atomicAdd(&g_cur[d], 1);
        g_csr[p] = s;
    }
}

// ---------------------------------------------------------------------------
// Gather-aggregate: agg[n] = mean over in-edges of h[src]. 16 lanes per node,
// each lane owns one float4 column segment. No atomics, no zeroing pass.
// ---------------------------------------------------------------------------
__global__ void __launch_bounds__(256) k_aggregate() {
    const int gt = blockIdx.x * 256 + threadIdx.x;
    const int n = gt >> 4;
    if (n >= N_NODES) return;
    const int q = gt & 15;

    const int s0 = g_off[n];
    const int cnt = g_deg[n];
    float4 acc = make_float4(0.f, 0.f, 0.f, 0.f);
#pragma unroll 4
    for (int i = 0; i < cnt; i++) {
        const int s = g_csr[s0 + i];
        const float4 v = *(const float4*)(g_h + (size_t)s * HID + q * 4);
        acc.x += v.x; acc.y += v.y; acc.z += v.z; acc.w += v.w;
    }
    const float inv = g_inv[n];
    acc.x *= inv; acc.y *= inv; acc.z *= inv; acc.w *= inv;
    *(float4*)(g_agg + (size_t)n * HID + q * 4) = acc;
}

// ---------------------------------------------------------------------------
// Layer: h = relu(h + agg @ Wl + bl + h @ Wr)  (agg is already the mean)
// One thread per node, both 64x64 weights in smem (broadcast reads).
// ---------------------------------------------------------------------------
__global__ void __launch_bounds__(256) k_layer(const float* __restrict__ Wl,
                                               const float* __restrict__ bl,
                                               const float* __restrict__ Wr) {
    __shared__ float Wls[HID * HID];
    __shared__ float Wrs[HID * HID];
    const int tid = threadIdx.x;
#pragma unroll
    for (int i = tid; i < HID * HID / 4; i += 256) {
        ((float4*)Wls)[i] = ((const float4*)Wl)[i];
        ((float4*)Wrs)[i] = ((const float4*)Wr)[i];
    }
    __syncthreads();

    const int row = blockIdx.x * 256 + tid;
    if (row >= N_NODES) return;

    float acc[HID];
#pragma unroll
    for (int j = 0; j < HID; j++) acc[j] = bl[j];

    const float4* ar = (const float4*)(g_agg + (size_t)row * HID);
    const float4* hr = (const float4*)(g_h + (size_t)row * HID);

#pragma unroll 1
    for (int k4 = 0; k4 < HID / 4; k4++) {
        const float4 av = ar[k4];
        const float4 hv = hr[k4];
        const int k = k4 * 4;
        const float* wl0 = Wls + k * HID;
        const float* wr0 = Wrs + k * HID;
#pragma unroll
        for (int j = 0; j < HID; j++) {
            float a = acc[j];
            a = fmaf(av.x, wl0[j],           a);
            a = fmaf(av.y, wl0[HID + j],     a);
            a = fmaf(av.z, wl0[2 * HID + j], a);
            a = fmaf(av.w, wl0[3 * HID + j], a);
            a = fmaf(hv.x, wr0[j],           a);
            a = fmaf(hv.y, wr0[HID + j],     a);
            a = fmaf(hv.z, wr0[2 * HID + j], a);
            a = fmaf(hv.w, wr0[3 * HID + j], a);
            acc[j] = a;
        }
    }

    // residual + relu, in place
    float4* ho = (float4*)(g_h + (size_t)row * HID);
#pragma unroll
    for (int j4 = 0; j4 < HID / 4; j4++) {
        float4 hv = hr[j4];
        float4 o;
        o.x = fmaxf(hv.x + acc[4 * j4 + 0], 0.f);
        o.y = fmaxf(hv.y + acc[4 * j4 + 1], 0.f);
        o.z = fmaxf(hv.z + acc[4 * j4 + 2], 0.f);
        o.w = fmaxf(hv.w + acc[4 * j4 + 3], 0.f);
        ho[j4] = o;
    }
}

// ---------------------------------------------------------------------------
// Head: out = sigmoid(h @ W_cls + b_cls)
// ---------------------------------------------------------------------------
__global__ void k_final(const float* __restrict__ Wc,
                        const float* __restrict__ bc,
                        float* __restrict__ out) {
    int row = blockIdx.x * blockDim.x + threadIdx.x;
    if (row >= N_NODES) return;
    float s = bc[0];
    const float4* hr = (const float4*)(g_h + (size_t)row * HID);
#pragma unroll
    for (int j4 = 0; j4 < HID / 4; j4++) {
        float4 h = hr[j4];
        float4 w = ((const float4*)Wc)[j4];
        s = fmaf(h.x, w.x, s);
        s = fmaf(h.y, w.y, s);
        s = fmaf(h.z, w.z, s);
        s = fmaf(h.w, w.w, s);
    }
    out[row] = 1.0f / (1.0f + expf(-s));
}

// ---------------------------------------------------------------------------
extern "C" void kernel_launch(void* const* d_in, const int* in_sizes, int n_in,
                              void* d_out, int out_size) {
    const float* x     = (const float*)d_in[0];
    const int*   ei    = (const int*)d_in[1];     // int32 [2, E] (JAX x64 off)
    const float* W_enc = (const float*)d_in[2];
    const float* b_enc = (const float*)d_in[3];
    const float* Wl    = (const float*)d_in[4];
    const float* bl    = (const float*)d_in[5];
    const float* Wr    = (const float*)d_in[6];
    const float* W_cls = (const float*)d_in[7];
    const float* b_cls = (const float*)d_in[8];
    float* out = (float*)d_out;

    const int nb_nodes = (N_NODES + 255) / 256;
    const int nb_edges = (N_EDGES + 255) / 256;

    k_encoder<<<nb_nodes, 256>>>(x, W_enc, b_enc);

    // CSR build
    k_zero_deg<<<nb_nodes, 256>>>();
    k_count<<<nb_edges, 256>>>(ei);
    k_inv<<<nb_nodes, 256>>>();
    k_scan1<<<NB_SCAN, 256>>>();
    k_scan2<<<1, 128>>>();
    k_scan3<<<nb_nodes, 256>>>();
    k_bin<<<nb_edges, 256>>>(ei);

    for (int l = 0; l < NL; l++) {
        k_aggregate<<<(N_NODES * 16 + 255) / 256, 256>>>();
        k_layer<<<nb_nodes, 256>>>(Wl + (size_t)l * HID * HID,
                                   bl + (size_t)l * HID,
                                   Wr + (size_t)l * HID * HID);
    }

    k_final<<<nb_nodes, 256>>>(W_cls, b_cls, out);
}

// round 5
// speedup vs baseline: 1.3349x; 1.3349x over previous
#include <cuda_runtime.h>
#include <math.h>

#define N_NODES 100000
#define N_EDGES 1600000
#define IN_DIM  512
#define HID     64
#define NL      3

#define SCAN_CHUNK 1024
#define NB_SCAN ((N_NODES + SCAN_CHUNK - 1) / SCAN_CHUNK)   // 98

// Scratch (device globals: allowed; cudaMalloc is not)
__device__ __align__(16) float g_h[N_NODES * HID];
__device__ __align__(16) float g_agg[N_NODES * HID];
__device__ float g_inv[N_NODES];
__device__ int   g_deg[N_NODES];
__device__ int   g_off[N_NODES];
__device__ int   g_cur[N_NODES];
__device__ int   g_csr[N_EDGES];
__device__ int   g_bsum[NB_SCAN];
__device__ int   g_bpre[NB_SCAN];

__device__ __forceinline__ unsigned f2tf32(float v) {
    unsigned u;
    asm("cvt.rna.tf32.f32 %0, %1;" : "=r"(u) : "f"(v));
    return u;
}

// ---------------------------------------------------------------------------
// Encoder: h = x @ W_enc + b_enc   ([100k,512] @ [512,64])  — tf32 mma.sync
// Block: 256 threads (8 warps). Block tile M=128, N=64, K-chunk=32.
// Warp w owns rows [w*16, w*16+16), all 64 cols (8 n-tiles of m16n8k8).
// smem staged pre-converted to tf32; padded stride 36 => conflict-free frags.
// ---------------------------------------------------------------------------
__global__ void __launch_bounds__(256) k_encoder(const float* __restrict__ x,
                                                 const float* __restrict__ W,
                                                 const float* __restrict__ bias) {
    __shared__ unsigned As[128 * 36];   // A tile (tf32 bits), row stride 36
    __shared__ unsigned Bt[64 * 36];    // B tile transposed [n][k], stride 36

    const int tid  = threadIdx.x;
    const int lane = tid & 31;
    const int warp = tid >> 5;
    const int g    = lane >> 2;   // group id (row within frag)
    const int t4   = lane & 3;    // thread-in-group (col within frag)
    const int rowBase = blockIdx.x * 128;

    float acc[8][4];
#pragma unroll
    for (int nt = 0; nt < 8; nt++)
#pragma unroll
        for (int c = 0; c < 4; c++) acc[nt][c] = 0.f;

    for (int kc = 0; kc < IN_DIM; kc += 32) {
        __syncthreads();
        // ---- stage A: 128 rows x 32 cols. 4 float4 per thread. ----
        {
            const int r  = tid >> 1;
            const int c0 = (tid & 1) * 16;
            int gr = rowBase + r;
            if (gr >= N_NODES) gr = N_NODES - 1;
            const float4* src = (const float4*)(x + (size_t)gr * IN_DIM + kc + c0);
#pragma unroll
            for (int j = 0; j < 4; j++) {
                float4 v = src[j];
                uint4 u;
                u.x = f2tf32(v.x); u.y = f2tf32(v.y);
                u.z = f2tf32(v.z); u.w = f2tf32(v.w);
                *(uint4*)&As[r * 36 + c0 + j * 4] = u;
            }
        }
        // ---- stage B transposed: 32 k-rows x 64 n-cols. 2 float4 per thread. ----
#pragma unroll
        for (int j = 0; j < 2; j++) {
            const int f  = tid * 2 + j;
            const int k  = f >> 4;
            const int n0 = (f & 15) * 4;
            const float4 v = *(const float4*)(W + (size_t)(kc + k) * HID + n0);
            Bt[(n0 + 0) * 36 + k] = f2tf32(v.x);
            Bt[(n0 + 1) * 36 + k] = f2tf32(v.y);
            Bt[(n0 + 2) * 36 + k] = f2tf32(v.z);
            Bt[(n0 + 3) * 36 + k] = f2tf32(v.w);
        }
        __syncthreads();

        // ---- 4 k-steps of m16n8k8 ----
#pragma unroll
        for (int kk = 0; kk < 4; kk++) {
            const int k0 = kk * 8;
            const unsigned a0 = As[(warp * 16 + g) * 36 + k0 + t4];
            const unsigned a1 = As[(warp * 16 + g + 8) * 36 + k0 + t4];
            const unsigned a2 = As[(warp * 16 + g) * 36 + k0 + t4 + 4];
            const unsigned a3 = As[(warp * 16 + g + 8) * 36 + k0 + t4 + 4];
#pragma unroll
            for (int nt = 0; nt < 8; nt++) {
                const unsigned b0 = Bt[(nt * 8 + g) * 36 + k0 + t4];
                const unsigned b1 = Bt[(nt * 8 + g) * 36 + k0 + t4 + 4];
                asm volatile(
                    "mma.sync.aligned.m16n8k8.row.col.f32.tf32.tf32.f32 "
                    "{%0,%1,%2,%3}, {%4,%5,%6,%7}, {%8,%9}, {%0,%1,%2,%3};"
                    : "+f"(acc[nt][0]), "+f"(acc[nt][1]),
                      "+f"(acc[nt][2]), "+f"(acc[nt][3])
                    : "r"(a0), "r"(a1), "r"(a2), "r"(a3), "r"(b0), "r"(b1));
            }
        }
    }

    // ---- epilogue: add bias, store to g_h ----
    const int r0 = rowBase + warp * 16 + g;
    const int r1 = r0 + 8;
#pragma unroll
    for (int nt = 0; nt < 8; nt++) {
        const int col = nt * 8 + t4 * 2;
        const float b0 = bias[col], b1 = bias[col + 1];
        if (r0 < N_NODES) {
            float2 o = make_float2(acc[nt][0] + b0, acc[nt][1] + b1);
            *(float2*)(g_h + (size_t)r0 * HID + col) = o;
        }
        if (r1 < N_NODES) {
            float2 o = make_float2(acc[nt][2] + b0, acc[nt][3] + b1);
            *(float2*)(g_h + (size_t)r1 * HID + col) = o;
        }
    }
}

// ---------------------------------------------------------------------------
// Degree + CSR construction  (edge_index is int32: [2, E] row-major)
// ---------------------------------------------------------------------------
__global__ void k_zero_deg() {
    int i = blockIdx.x * blockDim.x + threadIdx.x;
    if (i < N_NODES) { g_deg[i] = 0; g_cur[i] = 0; }
}

__global__ void k_count(const int* __restrict__ ei) {
    int e = blockIdx.x * blockDim.x + threadIdx.x;
    if (e < N_EDGES) atomicAdd(&g_deg[ei[N_EDGES + e]], 1);
}

__global__ void k_inv() {
    int i = blockIdx.x * blockDim.x + threadIdx.x;
    if (i < N_NODES) {
        int d = g_deg[i];
        g_inv[i] = (d > 0) ? (1.0f / (float)d) : 0.0f;
    }
}

__global__ void __launch_bounds__(256) k_scan1() {
    __shared__ int s_sum[256];
    const int b = blockIdx.x, t = threadIdx.x;
    const int base = b * SCAN_CHUNK + t * 4;
    int v[4], tot = 0;
#pragma unroll
    for (int j = 0; j < 4; j++) {
        int idx = base + j;
        v[j] = (idx < N_NODES) ? g_deg[idx] : 0;
        tot += v[j];
    }
    s_sum[t] = tot;
    __syncthreads();
    for (int off = 1; off < 256; off <<= 1) {
        int x = (t >= off) ? s_sum[t - off] : 0;
        __syncthreads();
        s_sum[t] += x;
        __syncthreads();
    }
    int run = s_sum[t] - tot;
#pragma unroll
    for (int j = 0; j < 4; j++) {
        int idx = base + j;
        if (idx < N_NODES) g_off[idx] = run;
        run += v[j];
    }
    if (t == 255) g_bsum[b] = s_sum[255];
}

__global__ void __launch_bounds__(128) k_scan2() {
    __shared__ int s[128];
    const int t = threadIdx.x;
    int v = (t < NB_SCAN) ? g_bsum[t] : 0;
    s[t] = v;
    __syncthreads();
    for (int off = 1; off < 128; off <<= 1) {
        int x = (t >= off) ? s[t - off] : 0;
        __syncthreads();
        s[t] += x;
        __syncthreads();
    }
    if (t < NB_SCAN) g_bpre[t] = s[t] - v;
}

__global__ void k_scan3() {
    int i = blockIdx.x * blockDim.x + threadIdx.x;
    if (i < N_NODES) g_off[i] += g_bpre[i / SCAN_CHUNK];
}

__global__ void k_bin(const int* __restrict__ ei) {
    int e = blockIdx.x * blockDim.x + threadIdx.x;
    if (e < N_EDGES) {
        int s = ei[e];
        int d = ei[N_EDGES + e];
        int p = g_off[d] + atomicAdd(&g_cur[d], 1);
        g_csr[p] = s;
    }
}

// ---------------------------------------------------------------------------
// Gather-aggregate: agg[n] = mean over in-edges of h[src]. 16 lanes per node.
// ---------------------------------------------------------------------------
__global__ void __launch_bounds__(256) k_aggregate() {
    const int gt = blockIdx.x * 256 + threadIdx.x;
    const int n = gt >> 4;
    if (n >= N_NODES) return;
    const int q = gt & 15;

    const int s0 = g_off[n];
    const int cnt = g_deg[n];
    float4 acc = make_float4(0.f, 0.f, 0.f, 0.f);
#pragma unroll 4
    for (int i = 0; i < cnt; i++) {
        const int s = g_csr[s0 + i];
        const float4 v = *(const float4*)(g_h + (size_t)s * HID + q * 4);
        acc.x += v.x; acc.y += v.y; acc.z += v.z; acc.w += v.w;
    }
    const float inv = g_inv[n];
    acc.x *= inv; acc.y *= inv; acc.z *= inv; acc.w *= inv;
    *(float4*)(g_agg + (size_t)n * HID + q * 4) = acc;
}

// ---------------------------------------------------------------------------
// Layer: h = relu(h + agg @ Wl + bl + h @ Wr). float4-vectorized smem reads.
// ---------------------------------------------------------------------------
__global__ void __launch_bounds__(256) k_layer(const float* __restrict__ Wl,
                                               const float* __restrict__ bl,
                                               const float* __restrict__ Wr) {
    __shared__ float Wls[HID * HID];
    __shared__ float Wrs[HID * HID];
    const int tid = threadIdx.x;
#pragma unroll
    for (int i = tid; i < HID * HID / 4; i += 256) {
        ((float4*)Wls)[i] = ((const float4*)Wl)[i];
        ((float4*)Wrs)[i] = ((const float4*)Wr)[i];
    }
    __syncthreads();

    const int row = blockIdx.x * 256 + tid;
    if (row >= N_NODES) return;

    float4 acc[16];
#pragma unroll
    for (int j4 = 0; j4 < 16; j4++) acc[j4] = ((const float4*)bl)[j4];

    const float4* ar = (const float4*)(g_agg + (size_t)row * HID);
    const float4* hr = (const float4*)(g_h + (size_t)row * HID);

#pragma unroll 1
    for (int k4 = 0; k4 < 16; k4++) {
        const float4 av = ar[k4];
        const float4 hv = hr[k4];
        const float* wl = Wls + k4 * 4 * HID;
        const float* wr = Wrs + k4 * 4 * HID;
#pragma unroll
        for (int j4 = 0; j4 < 16; j4++) {
            const float4 l0 = *(const float4*)(wl + j4 * 4);
            const float4 l1 = *(const float4*)(wl + HID + j4 * 4);
            const float4 l2 = *(const float4*)(wl + 2 * HID + j4 * 4);
            const float4 l3 = *(const float4*)(wl + 3 * HID + j4 * 4);
            const float4 r0 = *(const float4*)(wr + j4 * 4);
            const float4 r1 = *(const float4*)(wr + HID + j4 * 4);
            const float4 r2 = *(const float4*)(wr + 2 * HID + j4 * 4);
            const float4 r3 = *(const float4*)(wr + 3 * HID + j4 * 4);
            float4 a = acc[j4];
            a.x = fmaf(av.x, l0.x, a.x); a.y = fmaf(av.x, l0.y, a.y);
            a.z = fmaf(av.x, l0.z, a.z); a.w = fmaf(av.x, l0.w, a.w);
            a.x = fmaf(av.y, l1.x, a.x); a.y = fmaf(av.y, l1.y, a.y);
            a.z = fmaf(av.y, l1.z, a.z); a.w = fmaf(av.y, l1.w, a.w);
            a.x = fmaf(av.z, l2.x, a.x); a.y = fmaf(av.z, l2.y, a.y);
            a.z = fmaf(av.z, l2.z, a.z); a.w = fmaf(av.z, l2.w, a.w);
            a.x = fmaf(av.w, l3.x, a.x); a.y = fmaf(av.w, l3.y, a.y);
            a.z = fmaf(av.w, l3.z, a.z); a.w = fmaf(av.w, l3.w, a.w);
            a.x = fmaf(hv.x, r0.x, a.x); a.y = fmaf(hv.x, r0.y, a.y);
            a.z = fmaf(hv.x, r0.z, a.z); a.w = fmaf(hv.x, r0.w, a.w);
            a.x = fmaf(hv.y, r1.x, a.x); a.y = fmaf(hv.y, r1.y, a.y);
            a.z = fmaf(hv.y, r1.z, a.z); a.w = fmaf(hv.y, r1.w, a.w);
            a.x = fmaf(hv.z, r2.x, a.x); a.y = fmaf(hv.z, r2.y, a.y);
            a.z = fmaf(hv.z, r2.z, a.z); a.w = fmaf(hv.z, r2.w, a.w);
            a.x = fmaf(hv.w, r3.x, a.x); a.y = fmaf(hv.w, r3.y, a.y);
            a.z = fmaf(hv.w, r3.z, a.z); a.w = fmaf(hv.w, r3.w, a.w);
            acc[j4] = a;
        }
    }

    // residual + relu, in place
    float4* ho = (float4*)(g_h + (size_t)row * HID);
#pragma unroll
    for (int j4 = 0; j4 < 16; j4++) {
        float4 hv = hr[j4];
        float4 o;
        o.x = fmaxf(hv.x + acc[j4].x, 0.f);
        o.y = fmaxf(hv.y + acc[j4].y, 0.f);
        o.z = fmaxf(hv.z + acc[j4].z, 0.f);
        o.w = fmaxf(hv.w + acc[j4].w, 0.f);
        ho[j4] = o;
    }
}

// ---------------------------------------------------------------------------
// Head: out = sigmoid(h @ W_cls + b_cls)
// ---------------------------------------------------------------------------
__global__ void k_final(const float* __restrict__ Wc,
                        const float* __restrict__ bc,
                        float* __restrict__ out) {
    int row = blockIdx.x * blockDim.x + threadIdx.x;
    if (row >= N_NODES) return;
    float s = bc[0];
    const float4* hr = (const float4*)(g_h + (size_t)row * HID);
#pragma unroll
    for (int j4 = 0; j4 < HID / 4; j4++) {
        float4 h = hr[j4];
        float4 w = ((const float4*)Wc)[j4];
        s = fmaf(h.x, w.x, s);
        s = fmaf(h.y, w.y, s);
        s = fmaf(h.z, w.z, s);
        s = fmaf(h.w, w.w, s);
    }
    out[row] = 1.0f / (1.0f + expf(-s));
}

// ---------------------------------------------------------------------------
extern "C" void kernel_launch(void* const* d_in, const int* in_sizes, int n_in,
                              void* d_out, int out_size) {
    const float* x     = (const float*)d_in[0];
    const int*   ei    = (const int*)d_in[1];     // int32 [2, E]
    const float* W_enc = (const float*)d_in[2];
    const float* b_enc = (const float*)d_in[3];
    const float* Wl    = (const float*)d_in[4];
    const float* bl    = (const float*)d_in[5];
    const float* Wr    = (const float*)d_in[6];
    const float* W_cls = (const float*)d_in[7];
    const float* b_cls = (const float*)d_in[8];
    float* out = (float*)d_out;

    const int nb_nodes = (N_NODES + 255) / 256;
    const int nb_edges = (N_EDGES + 255) / 256;

    k_encoder<<<(N_NODES + 127) / 128, 256>>>(x, W_enc, b_enc);

    // CSR build
    k_zero_deg<<<nb_nodes, 256>>>();
    k_count<<<nb_edges, 256>>>(ei);
    k_inv<<<nb_nodes, 256>>>();
    k_scan1<<<NB_SCAN, 256>>>();
    k_scan2<<<1, 128>>>();
    k_scan3<<<nb_nodes, 256>>>();
    k_bin<<<nb_edges, 256>>>(ei);

    for (int l = 0; l < NL; l++) {
        k_aggregate<<<(N_NODES * 16 + 255) / 256, 256>>>();
        k_layer<<<nb_nodes, 256>>>(Wl + (size_t)l * HID * HID,
                                   bl + (size_t)l * HID,
                                   Wr + (size_t)l * HID * HID);
    }

    k_final<<<nb_nodes, 256>>>(W_cls, b_cls, out);
}

// round 6
// speedup vs baseline: 1.9255x; 1.4425x over previous
#include <cuda_runtime.h>
#include <math.h>

#define N_NODES 100000
#define N_EDGES 1600000
#define IN_DIM  512
#define HID     64
#define NL      3

#define SCAN_CHUNK 1024
#define NB_SCAN ((N_NODES + SCAN_CHUNK - 1) / SCAN_CHUNK)   // 98

// Scratch (device globals)
__device__ __align__(16) float g_h[N_NODES * HID];
__device__ __align__(16) float g_agg[N_NODES * HID];
__device__ float g_inv[N_NODES];
__device__ int   g_deg[N_NODES];
__device__ int   g_off[N_NODES];     // per-chunk-local exclusive prefix
__device__ int   g_cur[N_NODES];
__device__ int   g_csr[N_EDGES];
__device__ int   g_bsum[NB_SCAN];
__device__ int   g_bpre[NB_SCAN];    // chunk prefix (added on the fly)

__device__ __forceinline__ unsigned f2tf32(float v) {
    unsigned u;
    asm("cvt.rna.tf32.f32 %0, %1;" : "=r"(u) : "f"(v));
    return u;
}

// ---------------------------------------------------------------------------
// Encoder: h = x @ W_enc + b_enc   ([100k,512] @ [512,64])  — tf32 mma.sync
// ---------------------------------------------------------------------------
__global__ void __launch_bounds__(256) k_encoder(const float* __restrict__ x,
                                                 const float* __restrict__ W,
                                                 const float* __restrict__ bias) {
    __shared__ unsigned As[128 * 36];
    __shared__ unsigned Bt[64 * 36];

    const int tid  = threadIdx.x;
    const int lane = tid & 31;
    const int warp = tid >> 5;
    const int g    = lane >> 2;
    const int t4   = lane & 3;
    const int rowBase = blockIdx.x * 128;

    float acc[8][4];
#pragma unroll
    for (int nt = 0; nt < 8; nt++)
#pragma unroll
        for (int c = 0; c < 4; c++) acc[nt][c] = 0.f;

    for (int kc = 0; kc < IN_DIM; kc += 32) {
        __syncthreads();
        {
            const int r  = tid >> 1;
            const int c0 = (tid & 1) * 16;
            int gr = rowBase + r;
            if (gr >= N_NODES) gr = N_NODES - 1;
            const float4* src = (const float4*)(x + (size_t)gr * IN_DIM + kc + c0);
#pragma unroll
            for (int j = 0; j < 4; j++) {
                float4 v = src[j];
                uint4 u;
                u.x = f2tf32(v.x); u.y = f2tf32(v.y);
                u.z = f2tf32(v.z); u.w = f2tf32(v.w);
                *(uint4*)&As[r * 36 + c0 + j * 4] = u;
            }
        }
#pragma unroll
        for (int j = 0; j < 2; j++) {
            const int f  = tid * 2 + j;
            const int k  = f >> 4;
            const int n0 = (f & 15) * 4;
            const float4 v = *(const float4*)(W + (size_t)(kc + k) * HID + n0);
            Bt[(n0 + 0) * 36 + k] = f2tf32(v.x);
            Bt[(n0 + 1) * 36 + k] = f2tf32(v.y);
            Bt[(n0 + 2) * 36 + k] = f2tf32(v.z);
            Bt[(n0 + 3) * 36 + k] = f2tf32(v.w);
        }
        __syncthreads();

#pragma unroll
        for (int kk = 0; kk < 4; kk++) {
            const int k0 = kk * 8;
            const unsigned a0 = As[(warp * 16 + g) * 36 + k0 + t4];
            const unsigned a1 = As[(warp * 16 + g + 8) * 36 + k0 + t4];
            const unsigned a2 = As[(warp * 16 + g) * 36 + k0 + t4 + 4];
            const unsigned a3 = As[(warp * 16 + g + 8) * 36 + k0 + t4 + 4];
#pragma unroll
            for (int nt = 0; nt < 8; nt++) {
                const unsigned b0 = Bt[(nt * 8 + g) * 36 + k0 + t4];
                const unsigned b1 = Bt[(nt * 8 + g) * 36 + k0 + t4 + 4];
                asm volatile(
                    "mma.sync.aligned.m16n8k8.row.col.f32.tf32.tf32.f32 "
                    "{%0,%1,%2,%3}, {%4,%5,%6,%7}, {%8,%9}, {%0,%1,%2,%3};"
                    : "+f"(acc[nt][0]), "+f"(acc[nt][1]),
                      "+f"(acc[nt][2]), "+f"(acc[nt][3])
                    : "r"(a0), "r"(a1), "r"(a2), "r"(a3), "r"(b0), "r"(b1));
            }
        }
    }

    const int r0 = rowBase + warp * 16 + g;
    const int r1 = r0 + 8;
#pragma unroll
    for (int nt = 0; nt < 8; nt++) {
        const int col = nt * 8 + t4 * 2;
        const float b0 = bias[col], b1 = bias[col + 1];
        if (r0 < N_NODES)
            *(float2*)(g_h + (size_t)r0 * HID + col) =
                make_float2(acc[nt][0] + b0, acc[nt][1] + b1);
        if (r1 < N_NODES)
            *(float2*)(g_h + (size_t)r1 * HID + col) =
                make_float2(acc[nt][2] + b0, acc[nt][3] + b1);
    }
}

// ---------------------------------------------------------------------------
// Layer GEMM via tf32 mma:  hnew = [agg|h] @ [Wl;Wr] + bl ; h = relu(h+hnew)
// LAST: instead of storing h, compute out = sigmoid(dot(hfinal, Wc) + bc).
// ---------------------------------------------------------------------------
template <bool LAST>
__global__ void __launch_bounds__(256) k_layer_mma(const float* __restrict__ Wl,
                                                   const float* __restrict__ bl,
                                                   const float* __restrict__ Wr,
                                                   const float* __restrict__ Wc,
                                                   const float* __restrict__ bc,
                                                   float* __restrict__ out) {
    __shared__ unsigned As[128 * 36];
    __shared__ unsigned Bt[64 * 36];

    const int tid  = threadIdx.x;
    const int lane = tid & 31;
    const int warp = tid >> 5;
    const int g    = lane >> 2;
    const int t4   = lane & 3;
    const int rowBase = blockIdx.x * 128;

    float acc[8][4];
#pragma unroll
    for (int nt = 0; nt < 8; nt++)
#pragma unroll
        for (int c = 0; c < 4; c++) acc[nt][c] = 0.f;

    // 4 K-chunks of 32: chunks 0-1 from (agg, Wl), chunks 2-3 from (h, Wr)
#pragma unroll 1
    for (int kc = 0; kc < 4; kc++) {
        const float* Asrc = (kc < 2) ? g_agg : g_h;
        const float* Wsrc = (kc < 2) ? Wl : Wr;
        const int koff = (kc & 1) * 32;

        __syncthreads();
        {
            const int r  = tid >> 1;
            const int c0 = (tid & 1) * 16;
            int gr = rowBase + r;
            if (gr >= N_NODES) gr = N_NODES - 1;
            const float4* src = (const float4*)(Asrc + (size_t)gr * HID + koff + c0);
#pragma unroll
            for (int j = 0; j < 4; j++) {
                float4 v = src[j];
                uint4 u;
                u.x = f2tf32(v.x); u.y = f2tf32(v.y);
                u.z = f2tf32(v.z); u.w = f2tf32(v.w);
                *(uint4*)&As[r * 36 + c0 + j * 4] = u;
            }
        }
#pragma unroll
        for (int j = 0; j < 2; j++) {
            const int f  = tid * 2 + j;
            const int k  = f >> 4;
            const int n0 = (f & 15) * 4;
            const float4 v = *(const float4*)(Wsrc + (size_t)(koff + k) * HID + n0);
            Bt[(n0 + 0) * 36 + k] = f2tf32(v.x);
            Bt[(n0 + 1) * 36 + k] = f2tf32(v.y);
            Bt[(n0 + 2) * 36 + k] = f2tf32(v.z);
            Bt[(n0 + 3) * 36 + k] = f2tf32(v.w);
        }
        __syncthreads();

#pragma unroll
        for (int kk = 0; kk < 4; kk++) {
            const int k0 = kk * 8;
            const unsigned a0 = As[(warp * 16 + g) * 36 + k0 + t4];
            const unsigned a1 = As[(warp * 16 + g + 8) * 36 + k0 + t4];
            const unsigned a2 = As[(warp * 16 + g) * 36 + k0 + t4 + 4];
            const unsigned a3 = As[(warp * 16 + g + 8) * 36 + k0 + t4 + 4];
#pragma unroll
            for (int nt = 0; nt < 8; nt++) {
                const unsigned b0 = Bt[(nt * 8 + g) * 36 + k0 + t4];
                const unsigned b1 = Bt[(nt * 8 + g) * 36 + k0 + t4 + 4];
                asm volatile(
                    "mma.sync.aligned.m16n8k8.row.col.f32.tf32.tf32.f32 "
                    "{%0,%1,%2,%3}, {%4,%5,%6,%7}, {%8,%9}, {%0,%1,%2,%3};"
                    : "+f"(acc[nt][0]), "+f"(acc[nt][1]),
                      "+f"(acc[nt][2]), "+f"(acc[nt][3])
                    : "r"(a0), "r"(a1), "r"(a2), "r"(a3), "r"(b0), "r"(b1));
            }
        }
    }

    // Epilogue: residual + bias + relu (+ optional fused head)
    const int r0 = rowBase + warp * 16 + g;
    const int r1 = r0 + 8;
    float s0 = 0.f, s1 = 0.f;
#pragma unroll
    for (int nt = 0; nt < 8; nt++) {
        const int col = nt * 8 + t4 * 2;
        const float b0 = bl[col], b1 = bl[col + 1];
        float wc0 = 0.f, wc1 = 0.f;
        if (LAST) { wc0 = Wc[col]; wc1 = Wc[col + 1]; }
        if (r0 < N_NODES) {
            float2 hv = *(const float2*)(g_h + (size_t)r0 * HID + col);
            float ox = fmaxf(hv.x + acc[nt][0] + b0, 0.f);
            float oy = fmaxf(hv.y + acc[nt][1] + b1, 0.f);
            if (LAST) { s0 = fmaf(ox, wc0, s0); s0 = fmaf(oy, wc1, s0); }
            else *(float2*)(g_h + (size_t)r0 * HID + col) = make_float2(ox, oy);
        }
        if (r1 < N_NODES) {
            float2 hv = *(const float2*)(g_h + (size_t)r1 * HID + col);
            float ox = fmaxf(hv.x + acc[nt][2] + b0, 0.f);
            float oy = fmaxf(hv.y + acc[nt][3] + b1, 0.f);
            if (LAST) { s1 = fmaf(ox, wc0, s1); s1 = fmaf(oy, wc1, s1); }
            else *(float2*)(g_h + (size_t)r1 * HID + col) = make_float2(ox, oy);
        }
    }
    if (LAST) {
        // reduce across the 4 lanes of each group (t4 = 0..3)
        s0 += __shfl_xor_sync(0xffffffffu, s0, 1);
        s0 += __shfl_xor_sync(0xffffffffu, s0, 2);
        s1 += __shfl_xor_sync(0xffffffffu, s1, 1);
        s1 += __shfl_xor_sync(0xffffffffu, s1, 2);
        if (t4 == 0) {
            const float bias = bc[0];
            if (r0 < N_NODES) out[r0] = 1.0f / (1.0f + expf(-(s0 + bias)));
            if (r1 < N_NODES) out[r1] = 1.0f / (1.0f + expf(-(s1 + bias)));
        }
    }
}

// ---------------------------------------------------------------------------
// Degree + CSR construction  (edge_index is int32: [2, E] row-major)
// ---------------------------------------------------------------------------
__global__ void k_zero_deg() {
    int i = blockIdx.x * blockDim.x + threadIdx.x;
    if (i < N_NODES) { g_deg[i] = 0; g_cur[i] = 0; }
}

__global__ void k_count(const int* __restrict__ ei) {
    int e = blockIdx.x * blockDim.x + threadIdx.x;
    if (e < N_EDGES) atomicAdd(&g_deg[ei[N_EDGES + e]], 1);
}

// scan pass 1 + inv fused: per-chunk exclusive scan of g_deg, plus g_inv.
__global__ void __launch_bounds__(256) k_scan1() {
    __shared__ int s_sum[256];
    const int b = blockIdx.x, t = threadIdx.x;
    const int base = b * SCAN_CHUNK + t * 4;
    int v[4], tot = 0;
#pragma unroll
    for (int j = 0; j < 4; j++) {
        int idx = base + j;
        v[j] = (idx < N_NODES) ? g_deg[idx] : 0;
        tot += v[j];
    }
    s_sum[t] = tot;
    __syncthreads();
    for (int off = 1; off < 256; off <<= 1) {
        int x = (t >= off) ? s_sum[t - off] : 0;
        __syncthreads();
        s_sum[t] += x;
        __syncthreads();
    }
    int run = s_sum[t] - tot;
#pragma unroll
    for (int j = 0; j < 4; j++) {
        int idx = base + j;
        if (idx < N_NODES) {
            g_off[idx] = run;
            g_inv[idx] = (v[j] > 0) ? (1.0f / (float)v[j]) : 0.0f;
        }
        run += v[j];
    }
    if (t == 255) g_bsum[b] = s_sum[255];
}

__global__ void __launch_bounds__(128) k_scan2() {
    __shared__ int s[128];
    const int t = threadIdx.x;
    int v = (t < NB_SCAN) ? g_bsum[t] : 0;
    s[t] = v;
    __syncthreads();
    for (int off = 1; off < 128; off <<= 1) {
        int x = (t >= off) ? s[t - off] : 0;
        __syncthreads();
        s[t] += x;
        __syncthreads();
    }
    if (t < NB_SCAN) g_bpre[t] = s[t] - v;
}

// Bin edges into CSR by destination (adds chunk prefix inline).
__global__ void k_bin(const int* __restrict__ ei) {
    int e = blockIdx.x * blockDim.x + threadIdx.x;
    if (e < N_EDGES) {
        int s = ei[e];
        int d = ei[N_EDGES + e];
        int p = g_off[d] + g_bpre[d / SCAN_CHUNK] + atomicAdd(&g_cur[d], 1);
        g_csr[p] = s;
    }
}

// ---------------------------------------------------------------------------
// Gather-aggregate: agg[n] = mean over in-edges of h[src]. 16 lanes per node.
// ---------------------------------------------------------------------------
__global__ void __launch_bounds__(256) k_aggregate() {
    const int gt = blockIdx.x * 256 + threadIdx.x;
    const int n = gt >> 4;
    if (n >= N_NODES) return;
    const int q = gt & 15;

    const int s0 = g_off[n] + g_bpre[n / SCAN_CHUNK];
    const int cnt = g_deg[n];
    float4 acc = make_float4(0.f, 0.f, 0.f, 0.f);
#pragma unroll 4
    for (int i = 0; i < cnt; i++) {
        const int s = g_csr[s0 + i];
        const float4 v = *(const float4*)(g_h + (size_t)s * HID + q * 4);
        acc.x += v.x; acc.y += v.y; acc.z += v.z; acc.w += v.w;
    }
    const float inv = g_inv[n];
    acc.x *= inv; acc.y *= inv; acc.z *= inv; acc.w *= inv;
    *(float4*)(g_agg + (size_t)n * HID + q * 4) = acc;
}

// ---------------------------------------------------------------------------
extern "C" void kernel_launch(void* const* d_in, const int* in_sizes, int n_in,
                              void* d_out, int out_size) {
    const float* x     = (const float*)d_in[0];
    const int*   ei    = (const int*)d_in[1];     // int32 [2, E]
    const float* W_enc = (const float*)d_in[2];
    const float* b_enc = (const float*)d_in[3];
    const float* Wl    = (const float*)d_in[4];
    const float* bl    = (const float*)d_in[5];
    const float* Wr    = (const float*)d_in[6];
    const float* W_cls = (const float*)d_in[7];
    const float* b_cls = (const float*)d_in[8];
    float* out = (float*)d_out;

    const int nb_nodes = (N_NODES + 255) / 256;
    const int nb_edges = (N_EDGES + 255) / 256;
    const int nb_mma   = (N_NODES + 127) / 128;

    k_encoder<<<nb_mma, 256>>>(x, W_enc, b_enc);

    // CSR build
    k_zero_deg<<<nb_nodes, 256>>>();
    k_count<<<nb_edges, 256>>>(ei);
    k_scan1<<<NB_SCAN, 256>>>();
    k_scan2<<<1, 128>>>();
    k_bin<<<nb_edges, 256>>>(ei);

    for (int l = 0; l < NL; l++) {
        k_aggregate<<<(N_NODES * 16 + 255) / 256, 256>>>();
        const float* wl = Wl + (size_t)l * HID * HID;
        const float* bb = bl + (size_t)l * HID;
        const float* wr = Wr + (size_t)l * HID * HID;
        if (l == NL - 1)
            k_layer_mma<true><<<nb_mma, 256>>>(wl, bb, wr, W_cls, b_cls, out);
        else
            k_layer_mma<false><<<nb_mma, 256>>>(wl, bb, wr, W_cls, b_cls, out);
    }
}